// round 1
// baseline (speedup 1.0000x reference)
#include <cuda_runtime.h>
#include <cstdint>

#define WS     32
#define STRIDE 16
#define HDIM   2048
#define NUM    127            // (2048-32)/16 + 1
#define NP     (NUM * NUM)    // 16129
#define NCH    3
#define NGR    6

// ---- device scratch (no allocations allowed) ----
__device__ float              g_W[WS * WS];
__device__ float              g_grades[NP];
__device__ int                g_sel[4];

// ============================================================
// Kernel 0: fold grade_masks/ftnum/weights into one 32x32 map
//   W[a,b] = sum_g weights[g] * mask_g[a,b] / ftnum[g]
// ============================================================
__global__ void k_prep(const float* __restrict__ gm,
                       const float* __restrict__ ft,
                       const float* __restrict__ wt) {
    int idx = blockIdx.x * blockDim.x + threadIdx.x;
    if (idx < WS * WS) {
        float w = 0.f;
#pragma unroll
        for (int g = 0; g < NGR; ++g)
            w += gm[g * WS * WS + idx] * (wt[g] / ft[g]);
        g_W[idx] = w;
    }
}

// ============================================================
// Kernel 1: per-patch grade.
// One block (128 thr) per patch. Thread (ty,tx) owns 8 rows
// a = ty*8+i for all 3 channels -> 24 fp32 accumulators.
//   mm1: T = D * P          (P lane-varying, D broadcast, shared over ch)
//   mm2: X = T * D^T        (T lane-varying via row=tx, D broadcast)
//   grade += W[a,b]*log(|X|+1)
// ============================================================
__global__ __launch_bounds__(128) void k_grade(const float* __restrict__ x,
                                               const float* __restrict__ dct) {
    __shared__ float sD[WS][WS + 1];
    __shared__ float sP[NCH][WS][WS + 1];   // reused as T after mm1
    __shared__ float sW[WS][WS + 1];
    __shared__ float red[4];

    const int tid = threadIdx.x;
    const int tx  = tid & 31;
    const int ty  = tid >> 5;
    const int cx  = blockIdx.x;
    const int ry  = blockIdx.y;

    for (int e = tid; e < WS * WS; e += 128) {
        sD[e >> 5][e & 31] = dct[e];
        sW[e >> 5][e & 31] = g_W[e];
    }
    const int row0 = ry * STRIDE;
    const int col0 = cx * STRIDE;
    for (int e = tid; e < NCH * WS * WS; e += 128) {
        int c = e >> 10, r = (e >> 5) & 31, col = e & 31;
        sP[c][r][col] = x[((size_t)c * HDIM + (row0 + r)) * HDIM + col0 + col];
    }
    __syncthreads();

    float acc[NCH][8];
#pragma unroll
    for (int c = 0; c < NCH; ++c)
#pragma unroll
        for (int i = 0; i < 8; ++i) acc[c][i] = 0.f;

    // mm1: T[a][tx] = sum_b D[a][b] * P[c][b][tx]
#pragma unroll 8
    for (int b = 0; b < WS; ++b) {
        float p0 = sP[0][b][tx];
        float p1 = sP[1][b][tx];
        float p2 = sP[2][b][tx];
#pragma unroll
        for (int i = 0; i < 8; ++i) {
            float dv = sD[ty * 8 + i][b];
            acc[0][i] = fmaf(dv, p0, acc[0][i]);
            acc[1][i] = fmaf(dv, p1, acc[1][i]);
            acc[2][i] = fmaf(dv, p2, acc[2][i]);
        }
    }
    __syncthreads();                 // all P reads done
#pragma unroll
    for (int c = 0; c < NCH; ++c)
#pragma unroll
        for (int i = 0; i < 8; ++i)
            sP[c][ty * 8 + i][tx] = acc[c][i];   // overwrite P with T
    __syncthreads();

#pragma unroll
    for (int c = 0; c < NCH; ++c)
#pragma unroll
        for (int i = 0; i < 8; ++i) acc[c][i] = 0.f;

    // mm2: X[tx][e] = sum_d T[tx][d] * D[e][d]   (thread owns row tx, cols e=ty*8+i)
#pragma unroll 8
    for (int d = 0; d < WS; ++d) {
        float t0 = sP[0][tx][d];
        float t1 = sP[1][tx][d];
        float t2 = sP[2][tx][d];
#pragma unroll
        for (int i = 0; i < 8; ++i) {
            float dv = sD[ty * 8 + i][d];
            acc[0][i] = fmaf(t0, dv, acc[0][i]);
            acc[1][i] = fmaf(t1, dv, acc[1][i]);
            acc[2][i] = fmaf(t2, dv, acc[2][i]);
        }
    }

    float g = 0.f;
#pragma unroll
    for (int i = 0; i < 8; ++i) {
        int e = ty * 8 + i;
        float w = sW[tx][e];
        g += w * (__logf(fabsf(acc[0][i]) + 1.f) +
                  __logf(fabsf(acc[1][i]) + 1.f) +
                  __logf(fabsf(acc[2][i]) + 1.f));
    }
#pragma unroll
    for (int off = 16; off; off >>= 1)
        g += __shfl_down_sync(0xffffffffu, g, off);
    if (tx == 0) red[ty] = g;
    __syncthreads();
    if (tid == 0)
        g_grades[ry * NUM + cx] = red[0] + red[1] + red[2] + red[3];
}

// ============================================================
// Kernel 2: select indices of the two smallest and two largest
// grades under stable-argsort semantics. Keys = (bits<<32)|idx,
// valid because grades are >= 0 (u64 order == lexicographic
// (value, index) order).
// ============================================================
__global__ void k_select() {
    __shared__ unsigned long long sm1[256], sm2[256], sM1[256], sM2[256];
    const int tid = threadIdx.x;
    unsigned long long m1 = ~0ull, m2 = ~0ull, M1 = 0ull, M2 = 0ull;
    for (int i = tid; i < NP; i += 256) {
        unsigned long long k =
            ((unsigned long long)__float_as_uint(g_grades[i]) << 32) | (unsigned)i;
        if (k < m1) { m2 = m1; m1 = k; } else if (k < m2) { m2 = k; }
        if (k > M1) { M2 = M1; M1 = k; } else if (k > M2) { M2 = k; }
    }
    sm1[tid] = m1; sm2[tid] = m2; sM1[tid] = M1; sM2[tid] = M2;
    __syncthreads();
    for (int s = 128; s; s >>= 1) {
        if (tid < s) {
            unsigned long long a1 = sm1[tid], a2 = sm2[tid];
            unsigned long long b1 = sm1[tid + s], b2 = sm2[tid + s];
            unsigned long long n1 = (a1 < b1) ? a1 : b1;
            unsigned long long n2 = (a1 < b1) ? ((a2 < b1) ? a2 : b1)
                                              : ((b2 < a1) ? b2 : a1);
            sm1[tid] = n1; sm2[tid] = n2;
            unsigned long long A1 = sM1[tid], A2 = sM2[tid];
            unsigned long long B1 = sM1[tid + s], B2 = sM2[tid + s];
            unsigned long long X1 = (A1 > B1) ? A1 : B1;
            unsigned long long X2 = (A1 > B1) ? ((A2 > B1) ? A2 : B1)
                                              : ((B2 > A1) ? B2 : A1);
            sM1[tid] = X1; sM2[tid] = X2;
        }
        __syncthreads();
    }
    if (tid == 0) {
        g_sel[0] = (int)(sm1[0] & 0xffffffffull);   // order[0]
        g_sel[1] = (int)(sM1[0] & 0xffffffffull);   // order[-1]
        g_sel[2] = (int)(sm2[0] & 0xffffffffull);   // order[1]
        g_sel[3] = (int)(sM2[0] & 0xffffffffull);   // order[-2]
    }
}

// ============================================================
// Kernel 3: full level reconstruction for the 4 selected
// patches only. 12 blocks = 4 patches x 3 channels, 1024 thr.
//   level = D^T * ((D * P * D^T) .* mask) * D
// ============================================================
__global__ __launch_bounds__(1024) void k_level(const float* __restrict__ x,
                                                const float* __restrict__ dct,
                                                const float* __restrict__ mask,
                                                float* __restrict__ out) {
    __shared__ float sD[WS][WS + 1];
    __shared__ float sA[WS][WS + 1];
    __shared__ float sB[WS][WS + 1];
    __shared__ float sM[WS][WS + 1];

    const int tid = threadIdx.x;
    const int col = tid & 31;
    const int row = tid >> 5;
    const int o   = blockIdx.x / NCH;
    const int c   = blockIdx.x % NCH;

    const int p  = g_sel[o];
    const int ry = p / NUM;
    const int cx = p % NUM;

    sD[row][col] = dct[row * WS + col];
    sM[row][col] = mask[row * WS + col];
    sA[row][col] = x[((size_t)c * HDIM + ry * STRIDE + row) * HDIM
                     + cx * STRIDE + col];
    __syncthreads();

    // S1 = D * P
    float a = 0.f;
#pragma unroll 8
    for (int b = 0; b < WS; ++b) a = fmaf(sD[row][b], sA[b][col], a);
    sB[row][col] = a;
    __syncthreads();

    // Xm = (S1 * D^T) .* mask
    a = 0.f;
#pragma unroll 8
    for (int d = 0; d < WS; ++d) a = fmaf(sB[row][d], sD[col][d], a);
    a *= sM[row][col];
    sA[row][col] = a;          // S1 reads finished before prior sync
    __syncthreads();

    // Y = D^T * Xm
    a = 0.f;
#pragma unroll 8
    for (int b = 0; b < WS; ++b) a = fmaf(sD[b][row], sA[b][col], a);
    sB[row][col] = a;          // Xm-stage reads of sB finished before prior sync
    __syncthreads();

    // L = Y * D
    a = 0.f;
#pragma unroll 8
    for (int d = 0; d < WS; ++d) a = fmaf(sB[row][d], sD[d][col], a);

    out[((size_t)o * NCH + c) * (WS * WS) + row * WS + col] = a;
}

// ============================================================
// launch
// ============================================================
extern "C" void kernel_launch(void* const* d_in, const int* in_sizes, int n_in,
                              void* d_out, int out_size) {
    const float* x    = (const float*)d_in[0];
    const float* dct  = (const float*)d_in[1];
    const float* lmsk = (const float*)d_in[2];
    const float* gm   = (const float*)d_in[3];
    const float* ft   = (const float*)d_in[4];
    const float* wt   = (const float*)d_in[5];
    float*       out  = (float*)d_out;

    k_prep<<<4, 256>>>(gm, ft, wt);
    dim3 grid(NUM, NUM);
    k_grade<<<grid, 128>>>(x, dct);
    k_select<<<1, 256>>>();
    k_level<<<12, 1024>>>(x, dct, lmsk, out);
}

// round 2
// speedup vs baseline: 1.1556x; 1.1556x over previous
#include <cuda_runtime.h>
#include <cstdint>

#define WS     32
#define STRIDE 16
#define HDIM   2048
#define NUM    127            // (2048-32)/16 + 1
#define NP     (NUM * NUM)    // 16129
#define NCH    3
#define NGR    6

// ---- device scratch (no allocations allowed) ----
__device__ float g_W[WS * WS];
__device__ float g_grades[NP];
__device__ int   g_sel[4];

// ---- packed fp32x2 helpers (Blackwell FFMA2) ----
__device__ __forceinline__ unsigned long long pk2(float v) {
    unsigned long long r;
    asm("mov.b64 %0, {%1, %1};" : "=l"(r) : "f"(v));
    return r;
}
__device__ __forceinline__ unsigned long long fma2(unsigned long long a,
                                                   unsigned long long b,
                                                   unsigned long long c) {
    unsigned long long d;
    asm("fma.rn.f32x2 %0, %1, %2, %3;" : "=l"(d) : "l"(a), "l"(b), "l"(c));
    return d;
}
__device__ __forceinline__ float2 up2(unsigned long long v) {
    float2 f;
    asm("mov.b64 {%0, %1}, %2;" : "=f"(f.x), "=f"(f.y) : "l"(v));
    return f;
}

// ============================================================
// Kernel 0: fold grade_masks/ftnum/weights into one 32x32 map
// ============================================================
__global__ void k_prep(const float* __restrict__ gm,
                       const float* __restrict__ ft,
                       const float* __restrict__ wt) {
    int idx = blockIdx.x * blockDim.x + threadIdx.x;
    if (idx < WS * WS) {
        float w = 0.f;
#pragma unroll
        for (int g = 0; g < NGR; ++g)
            w += gm[g * WS * WS + idx] * (wt[g] / ft[g]);
        g_W[idx] = w;
    }
}

// ============================================================
// Kernel 1: per-patch grade, FFMA2-packed.
// 128 thr/block, one block per patch. Thread (ty,tx) owns rows
// a = ty*8 .. ty*8+7 as 4 packed f32x2 pairs, for all 3 ch.
//   mm1: T = D * P      mm2: X = T * D^T
//   grade += W[a,b]*log(|X|+1)
// D stored transposed (sDt[b][a]) so each a-pair is one LDS.64
// broadcast; P/T operand is broadcast-packed {v,v}.
// ============================================================
__global__ __launch_bounds__(128) void k_grade(const float* __restrict__ x,
                                               const float* __restrict__ dct) {
    __shared__ float sDt[WS][WS + 2];       // sDt[b][a] = D[a][b]; stride 34 (8B aligned rows)
    __shared__ float sP[NCH][WS][WS + 1];   // patch, reused as T after mm1
    __shared__ float sW[WS][WS + 1];
    __shared__ float red[4];

    const int tid = threadIdx.x;
    const int tx  = tid & 31;
    const int ty  = tid >> 5;
    const int a0  = ty * 8;
    const int cx  = blockIdx.x;
    const int ry  = blockIdx.y;

    for (int e = tid; e < WS * WS; e += 128) {
        int a = e >> 5, b = e & 31;
        sDt[b][a] = dct[e];
        sW[b][a]  = g_W[a * WS + b];        // sW[tx][e] layout == W[e][tx]? careful below
    }
    // NOTE: sW[i][j] now holds g_W[j*WS+i] == W[row=j][col=i]; we read sW[tx][e] = W[e][tx].
    // We need W[row=tx][col=e]; so instead store straight:
    // (overwrite with straight layout; tiny redundant cost, keeps indexing obvious)
    __syncthreads();
    for (int e = tid; e < WS * WS; e += 128)
        sW[e >> 5][e & 31] = g_W[e];

    const int row0 = ry * STRIDE;
    const int col0 = cx * STRIDE;
    for (int e = tid; e < NCH * WS * WS; e += 128) {
        int c = e >> 10, r = (e >> 5) & 31, col = e & 31;
        sP[c][r][col] = x[((size_t)c * HDIM + (row0 + r)) * HDIM + col0 + col];
    }
    __syncthreads();

    unsigned long long acc[NCH][4];
#pragma unroll
    for (int c = 0; c < NCH; ++c)
#pragma unroll
        for (int j = 0; j < 4; ++j) acc[c][j] = 0ull;

    // mm1: T[a][tx] = sum_b D[a][b] * P[c][b][tx]
#pragma unroll 8
    for (int b = 0; b < WS; ++b) {
        const unsigned long long* dvp =
            reinterpret_cast<const unsigned long long*>(&sDt[b][a0]);
        unsigned long long d0 = dvp[0], d1 = dvp[1], d2 = dvp[2], d3 = dvp[3];
        unsigned long long p0 = pk2(sP[0][b][tx]);
        unsigned long long p1 = pk2(sP[1][b][tx]);
        unsigned long long p2 = pk2(sP[2][b][tx]);
        acc[0][0] = fma2(d0, p0, acc[0][0]);
        acc[0][1] = fma2(d1, p0, acc[0][1]);
        acc[0][2] = fma2(d2, p0, acc[0][2]);
        acc[0][3] = fma2(d3, p0, acc[0][3]);
        acc[1][0] = fma2(d0, p1, acc[1][0]);
        acc[1][1] = fma2(d1, p1, acc[1][1]);
        acc[1][2] = fma2(d2, p1, acc[1][2]);
        acc[1][3] = fma2(d3, p1, acc[1][3]);
        acc[2][0] = fma2(d0, p2, acc[2][0]);
        acc[2][1] = fma2(d1, p2, acc[2][1]);
        acc[2][2] = fma2(d2, p2, acc[2][2]);
        acc[2][3] = fma2(d3, p2, acc[2][3]);
    }
    __syncthreads();                 // all P reads done
#pragma unroll
    for (int c = 0; c < NCH; ++c)
#pragma unroll
        for (int j = 0; j < 4; ++j) {
            float2 t = up2(acc[c][j]);
            sP[c][a0 + 2 * j][tx]     = t.x;   // overwrite P with T
            sP[c][a0 + 2 * j + 1][tx] = t.y;
        }
    __syncthreads();

#pragma unroll
    for (int c = 0; c < NCH; ++c)
#pragma unroll
        for (int j = 0; j < 4; ++j) acc[c][j] = 0ull;

    // mm2: X[tx][e] = sum_d T[tx][d] * D[e][d]
#pragma unroll 8
    for (int d = 0; d < WS; ++d) {
        const unsigned long long* dvp =
            reinterpret_cast<const unsigned long long*>(&sDt[d][a0]);
        unsigned long long e0 = dvp[0], e1 = dvp[1], e2 = dvp[2], e3 = dvp[3];
        unsigned long long t0 = pk2(sP[0][tx][d]);
        unsigned long long t1 = pk2(sP[1][tx][d]);
        unsigned long long t2 = pk2(sP[2][tx][d]);
        acc[0][0] = fma2(e0, t0, acc[0][0]);
        acc[0][1] = fma2(e1, t0, acc[0][1]);
        acc[0][2] = fma2(e2, t0, acc[0][2]);
        acc[0][3] = fma2(e3, t0, acc[0][3]);
        acc[1][0] = fma2(e0, t1, acc[1][0]);
        acc[1][1] = fma2(e1, t1, acc[1][1]);
        acc[1][2] = fma2(e2, t1, acc[1][2]);
        acc[1][3] = fma2(e3, t1, acc[1][3]);
        acc[2][0] = fma2(e0, t2, acc[2][0]);
        acc[2][1] = fma2(e1, t2, acc[2][1]);
        acc[2][2] = fma2(e2, t2, acc[2][2]);
        acc[2][3] = fma2(e3, t2, acc[2][3]);
    }

    float g = 0.f;
#pragma unroll
    for (int j = 0; j < 4; ++j) {
        int e = a0 + 2 * j;
        float2 v0 = up2(acc[0][j]);
        float2 v1 = up2(acc[1][j]);
        float2 v2 = up2(acc[2][j]);
        g += sW[tx][e] * (__logf(fabsf(v0.x) + 1.f) +
                          __logf(fabsf(v1.x) + 1.f) +
                          __logf(fabsf(v2.x) + 1.f));
        g += sW[tx][e + 1] * (__logf(fabsf(v0.y) + 1.f) +
                              __logf(fabsf(v1.y) + 1.f) +
                              __logf(fabsf(v2.y) + 1.f));
    }
#pragma unroll
    for (int off = 16; off; off >>= 1)
        g += __shfl_down_sync(0xffffffffu, g, off);
    if (tx == 0) red[ty] = g;
    __syncthreads();
    if (tid == 0)
        g_grades[ry * NUM + cx] = red[0] + red[1] + red[2] + red[3];
}

// ============================================================
// Kernel 2: two smallest + two largest grade indices,
// stable-argsort semantics via (bits<<32)|idx keys (grades>=0).
// ============================================================
__global__ __launch_bounds__(1024) void k_select() {
    __shared__ unsigned long long sm1[1024], sm2[1024], sM1[1024], sM2[1024];
    const int tid = threadIdx.x;
    unsigned long long m1 = ~0ull, m2 = ~0ull, M1 = 0ull, M2 = 0ull;
    for (int i = tid; i < NP; i += 1024) {
        unsigned long long k =
            ((unsigned long long)__float_as_uint(g_grades[i]) << 32) | (unsigned)i;
        if (k < m1) { m2 = m1; m1 = k; } else if (k < m2) { m2 = k; }
        if (k > M1) { M2 = M1; M1 = k; } else if (k > M2) { M2 = k; }
    }
    sm1[tid] = m1; sm2[tid] = m2; sM1[tid] = M1; sM2[tid] = M2;
    __syncthreads();
    for (int s = 512; s; s >>= 1) {
        if (tid < s) {
            unsigned long long a1 = sm1[tid], a2 = sm2[tid];
            unsigned long long b1 = sm1[tid + s], b2 = sm2[tid + s];
            unsigned long long n1 = (a1 < b1) ? a1 : b1;
            unsigned long long n2 = (a1 < b1) ? ((a2 < b1) ? a2 : b1)
                                              : ((b2 < a1) ? b2 : a1);
            sm1[tid] = n1; sm2[tid] = n2;
            unsigned long long A1 = sM1[tid], A2 = sM2[tid];
            unsigned long long B1 = sM1[tid + s], B2 = sM2[tid + s];
            unsigned long long X1 = (A1 > B1) ? A1 : B1;
            unsigned long long X2 = (A1 > B1) ? ((A2 > B1) ? A2 : B1)
                                              : ((B2 > A1) ? B2 : A1);
            sM1[tid] = X1; sM2[tid] = X2;
        }
        __syncthreads();
    }
    if (tid == 0) {
        g_sel[0] = (int)(sm1[0] & 0xffffffffull);   // order[0]
        g_sel[1] = (int)(sM1[0] & 0xffffffffull);   // order[-1]
        g_sel[2] = (int)(sm2[0] & 0xffffffffull);   // order[1]
        g_sel[3] = (int)(sM2[0] & 0xffffffffull);   // order[-2]
    }
}

// ============================================================
// Kernel 3: level reconstruction for the 4 selected patches.
//   level = D^T * ((D * P * D^T) .* mask) * D
// ============================================================
__global__ __launch_bounds__(1024) void k_level(const float* __restrict__ x,
                                                const float* __restrict__ dct,
                                                const float* __restrict__ mask,
                                                float* __restrict__ out) {
    __shared__ float sD[WS][WS + 1];
    __shared__ float sA[WS][WS + 1];
    __shared__ float sB[WS][WS + 1];
    __shared__ float sM[WS][WS + 1];

    const int tid = threadIdx.x;
    const int col = tid & 31;
    const int row = tid >> 5;
    const int o   = blockIdx.x / NCH;
    const int c   = blockIdx.x % NCH;

    const int p  = g_sel[o];
    const int ry = p / NUM;
    const int cx = p % NUM;

    sD[row][col] = dct[row * WS + col];
    sM[row][col] = mask[row * WS + col];
    sA[row][col] = x[((size_t)c * HDIM + ry * STRIDE + row) * HDIM
                     + cx * STRIDE + col];
    __syncthreads();

    float a = 0.f;
#pragma unroll 8
    for (int b = 0; b < WS; ++b) a = fmaf(sD[row][b], sA[b][col], a);
    sB[row][col] = a;
    __syncthreads();

    a = 0.f;
#pragma unroll 8
    for (int d = 0; d < WS; ++d) a = fmaf(sB[row][d], sD[col][d], a);
    a *= sM[row][col];
    sA[row][col] = a;
    __syncthreads();

    a = 0.f;
#pragma unroll 8
    for (int b = 0; b < WS; ++b) a = fmaf(sD[b][row], sA[b][col], a);
    sB[row][col] = a;
    __syncthreads();

    a = 0.f;
#pragma unroll 8
    for (int d = 0; d < WS; ++d) a = fmaf(sB[row][d], sD[d][col], a);

    out[((size_t)o * NCH + c) * (WS * WS) + row * WS + col] = a;
}

// ============================================================
// launch
// ============================================================
extern "C" void kernel_launch(void* const* d_in, const int* in_sizes, int n_in,
                              void* d_out, int out_size) {
    const float* x    = (const float*)d_in[0];
    const float* dct  = (const float*)d_in[1];
    const float* lmsk = (const float*)d_in[2];
    const float* gm   = (const float*)d_in[3];
    const float* ft   = (const float*)d_in[4];
    const float* wt   = (const float*)d_in[5];
    float*       out  = (float*)d_out;

    k_prep<<<4, 256>>>(gm, ft, wt);
    dim3 grid(NUM, NUM);
    k_grade<<<grid, 128>>>(x, dct);
    k_select<<<1, 1024>>>();
    k_level<<<12, 1024>>>(x, dct, lmsk, out);
}